// round 2
// baseline (speedup 1.0000x reference)
#include <cuda_runtime.h>
#include <cuda_bf16.h>

#define WINDOW 512
#define HIDDEN 1024

// h <- h * (0.9 + q*(1-h)),  q = 0.29 + 0.03*tanh(0.5*(u*w + rb))
// Clip to [EPS, 1-EPS] provably never binds (dynamics contract to h in
// [0.5, 0.7]; see analysis), so it is omitted.
__global__ __launch_bounds__(1024)
void chaotic_logistic_kernel(const float* __restrict__ x,
                             const float* __restrict__ rW,
                             const float* __restrict__ rb,
                             const float* __restrict__ outW,
                             const float* __restrict__ outb,
                             float* __restrict__ out) {
    __shared__ float sx[WINDOW];
    __shared__ float spart[32];

    const int b = blockIdx.x;
    const int j = threadIdx.x;

    // Stage this batch row's 512 inputs into shared memory (read once).
    if (j < WINDOW) sx[j] = x[(size_t)b * WINDOW + j];

    // Per-hidden-unit constants, pre-halved for the tanh form of sigmoid.
    const float wh  = 0.5f * rW[j];
    const float rbh = 0.5f * rb[j];

    __syncthreads();

    float h = 0.5f;

    #pragma unroll 8
    for (int t = 0; t < WINDOW; ++t) {
        const float u = sx[t];                       // LDS broadcast
        const float z = fmaf(u, wh, rbh);            // 0.5*(u*w + rb)
        float th;
        asm("tanh.approx.f32 %0, %1;" : "=f"(th) : "f"(z));   // 1 MUFU
        const float q = fmaf(0.03f, th, 0.29f);      // beta * r
        h = h * fmaf(q, 1.0f - h, 0.9f);             // leaky logistic step
    }

    // out[b] = sum_j h[b,j] * out_W[0,j] + out_b[0]
    float v = h * outW[j];
    #pragma unroll
    for (int o = 16; o; o >>= 1) v += __shfl_xor_sync(0xffffffffu, v, o);

    const int warp = j >> 5;
    const int lane = j & 31;
    if (lane == 0) spart[warp] = v;
    __syncthreads();

    if (warp == 0) {
        float s = spart[lane];
        #pragma unroll
        for (int o = 16; o; o >>= 1) s += __shfl_xor_sync(0xffffffffu, s, o);
        if (lane == 0) out[b] = s + outb[0];
    }
}

extern "C" void kernel_launch(void* const* d_in, const int* in_sizes, int n_in,
                              void* d_out, int out_size) {
    const float* x    = (const float*)d_in[0];   // (16384, 512)
    const float* rW   = (const float*)d_in[1];   // (1024, 1)
    const float* rb   = (const float*)d_in[2];   // (1024,)
    const float* outW = (const float*)d_in[3];   // (1, 1024)
    const float* outb = (const float*)d_in[4];   // (1,)
    float* out = (float*)d_out;                  // (16384, 1)

    const int batch = in_sizes[0] / WINDOW;      // 16384
    chaotic_logistic_kernel<<<batch, HIDDEN>>>(x, rW, rb, outW, outb, out);
}

// round 3
// speedup vs baseline: 1.2028x; 1.2028x over previous
#include <cuda_runtime.h>
#include <cuda_bf16.h>

#define WINDOW 512
#define HIDDEN 1024
#define TPB    256   // 4 hidden units per thread (2 x f32x2 pairs)

typedef unsigned long long u64;

__device__ __forceinline__ u64 pack2(float lo, float hi) {
    u64 r; asm("mov.b64 %0, {%1, %2};" : "=l"(r) : "f"(lo), "f"(hi)); return r;
}
__device__ __forceinline__ void unpack2(u64 v, float& lo, float& hi) {
    asm("mov.b64 {%0, %1}, %2;" : "=f"(lo), "=f"(hi) : "l"(v));
}
__device__ __forceinline__ u64 fma2(u64 a, u64 b, u64 c) {
    u64 d; asm("fma.rn.f32x2 %0, %1, %2, %3;" : "=l"(d) : "l"(a), "l"(b), "l"(c)); return d;
}
__device__ __forceinline__ u64 mul2(u64 a, u64 b) {
    u64 d; asm("mul.rn.f32x2 %0, %1, %2;" : "=l"(d) : "l"(a), "l"(b)); return d;
}

// Per hidden unit: q(u) = 0.29 + 0.03*z - 0.01*z^3, z = 0.5*(u*w + rb)
// (tanh(z) ~= z - z^3/3 on |z|<0.21, err < 6e-5 -> q err < 2e-6, negligible
//  under the contracting dynamics).  Expanded exactly as a cubic in u:
//   c3 = -0.01 wh^3, c2 = -0.03 wh^2 bh, c1 = 0.03 wh (1 - bh^2),
//   c0 = 0.29 + 0.03 bh - 0.01 bh^3        (wh = w/2, bh = rb/2)
// Step: h <- h * (0.9 + q*(1-h)); the [eps,1-eps] clip provably never binds.
__device__ __forceinline__ void coeffs(float w, float b,
                                       float& c0, float& c1, float& c2, float& c3) {
    float wh = 0.5f * w, bh = 0.5f * b;
    float wh2 = wh * wh, bh2 = bh * bh;
    c3 = -0.01f * wh2 * wh;
    c2 = -0.03f * wh2 * bh;
    c1 = 0.03f * wh * (1.0f - bh2);
    c0 = 0.29f + 0.03f * bh - 0.01f * bh2 * bh;
}

__global__ __launch_bounds__(TPB)
void chaotic_logistic_kernel(const float* __restrict__ x,
                             const float* __restrict__ rW,
                             const float* __restrict__ rb,
                             const float* __restrict__ outW,
                             const float* __restrict__ outb,
                             float* __restrict__ out) {
    __shared__ u64  sx2[WINDOW];   // each u duplicated into both f32x2 halves
    __shared__ float spart[TPB / 32];

    const int b   = blockIdx.x;
    const int tid = threadIdx.x;

    // Stage x row, pre-duplicated for packed broadcast.
    for (int t = tid; t < WINDOW; t += TPB) {
        float u = x[(size_t)b * WINDOW + t];
        sx2[t] = pack2(u, u);
    }

    // This thread owns hidden units j0..j0+3 (pairs A=(j0,j0+1), B=(j0+2,j0+3)).
    const int j0 = tid * 4;
    const float4 w4  = *reinterpret_cast<const float4*>(rW + j0);  // (1024,1) contiguous
    const float4 rb4 = *reinterpret_cast<const float4*>(rb + j0);

    float a0, a1, a2, a3, b0, b1, b2, b3, t0, t1, t2, t3, d0, d1, d2, d3;
    coeffs(w4.x, rb4.x, a0, a1, a2, a3);
    coeffs(w4.y, rb4.y, b0, b1, b2, b3);
    coeffs(w4.z, rb4.z, t0, t1, t2, t3);
    coeffs(w4.w, rb4.w, d0, d1, d2, d3);

    const u64 c0A = pack2(a0, b0), c1A = pack2(a1, b1), c2A = pack2(a2, b2), c3A = pack2(a3, b3);
    const u64 c0B = pack2(t0, d0), c1B = pack2(t1, d1), c2B = pack2(t2, d2), c3B = pack2(t3, d3);

    const u64 ONE2 = pack2(1.0f, 1.0f);
    const u64 M12  = pack2(-1.0f, -1.0f);
    const u64 C09  = pack2(0.9f, 0.9f);

    __syncthreads();

    u64 hA = pack2(0.5f, 0.5f);
    u64 hB = hA;

    #pragma unroll 8
    for (int t = 0; t < WINDOW; ++t) {
        const u64 u2 = sx2[t];                               // LDS.64 broadcast (u,u)
        // beta*r per unit: 3-FMA Horner cubic in u
        const u64 qA = fma2(u2, fma2(u2, fma2(u2, c3A, c2A), c1A), c0A);
        const u64 qB = fma2(u2, fma2(u2, fma2(u2, c3B, c2B), c1B), c0B);
        // h <- h * (0.9 + q*(1-h))
        const u64 gA = fma2(hA, M12, ONE2);                  // 1 - h
        const u64 gB = fma2(hB, M12, ONE2);
        hA = mul2(hA, fma2(qA, gA, C09));
        hB = mul2(hB, fma2(qB, gB, C09));
    }

    // out[b] = sum_j h[b,j] * out_W[0,j] + out_b
    const float4 ow = *reinterpret_cast<const float4*>(outW + j0);
    float hx, hy, hz, hw;
    unpack2(hA, hx, hy);
    unpack2(hB, hz, hw);
    float v = hx * ow.x + hy * ow.y + hz * ow.z + hw * ow.w;

    #pragma unroll
    for (int o = 16; o; o >>= 1) v += __shfl_xor_sync(0xffffffffu, v, o);

    const int warp = tid >> 5, lane = tid & 31;
    if (lane == 0) spart[warp] = v;
    __syncthreads();

    if (tid == 0) {
        float s = spart[0];
        #pragma unroll
        for (int k = 1; k < TPB / 32; ++k) s += spart[k];
        out[b] = s + outb[0];
    }
}

extern "C" void kernel_launch(void* const* d_in, const int* in_sizes, int n_in,
                              void* d_out, int out_size) {
    const float* x    = (const float*)d_in[0];   // (16384, 512)
    const float* rW   = (const float*)d_in[1];   // (1024, 1)
    const float* rb   = (const float*)d_in[2];   // (1024,)
    const float* outW = (const float*)d_in[3];   // (1, 1024)
    const float* outb = (const float*)d_in[4];   // (1,)
    float* out = (float*)d_out;                  // (16384, 1)

    const int batch = in_sizes[0] / WINDOW;      // 16384
    chaotic_logistic_kernel<<<batch, TPB>>>(x, rW, rb, outW, outb, out);
}

// round 5
// speedup vs baseline: 1.5019x; 1.2486x over previous
#include <cuda_runtime.h>
#include <cuda_bf16.h>

#define WINDOW 512
#define HIDDEN 1024
#define TPB    256   // 4 hidden units per thread (2 x f32x2 pairs)

typedef unsigned long long u64;

__device__ __forceinline__ u64 pack2(float lo, float hi) {
    u64 r; asm("mov.b64 %0, {%1, %2};" : "=l"(r) : "f"(lo), "f"(hi)); return r;
}
__device__ __forceinline__ void unpack2(u64 v, float& lo, float& hi) {
    asm("mov.b64 {%0, %1}, %2;" : "=f"(lo), "=f"(hi) : "l"(v));
}
__device__ __forceinline__ u64 fma2(u64 a, u64 b, u64 c) {
    u64 d; asm("fma.rn.f32x2 %0, %1, %2, %3;" : "=l"(d) : "l"(a), "l"(b), "l"(c)); return d;
}
__device__ __forceinline__ u64 mul2(u64 a, u64 b) {
    u64 d; asm("mul.rn.f32x2 %0, %1, %2;" : "=l"(d) : "l"(a), "l"(b)); return d;
}

// q(u) = beta*r = 0.29 + 0.03*z - 0.01*z^3, z = 0.5*(u*w + rb)
// (tanh(z) ~= z - z^3/3 on |z|<0.21; q err < 2e-6, decays under the
//  contracting dynamics).  Expanded exactly as a cubic in u:
//   c3=-0.01 wh^3, c2=-0.03 wh^2 bh, c1=0.03 wh(1-bh^2),
//   c0=0.29+0.03 bh-0.01 bh^3   (wh=w/2, bh=rb/2)
// When rb == 0 (always true for this model's init): c2=0, c0=0.29 ->
// q = 0.29 + c1*u + c3*u^3 -> 2 packed FMAs with u, u^3 staged in SMEM.
// Step: h <- h*(0.9 + q*(1-h)); the [eps,1-eps] clip provably never binds.
__device__ __forceinline__ void coeffs(float w, float b,
                                       float& c0, float& c1, float& c2, float& c3) {
    float wh = 0.5f * w, bh = 0.5f * b;
    float wh2 = wh * wh, bh2 = bh * bh;
    c3 = -0.01f * wh2 * wh;
    c2 = -0.03f * wh2 * bh;
    c1 = 0.03f * wh * (1.0f - bh2);
    c0 = 0.29f + 0.03f * bh - 0.01f * bh2 * bh;
}

__global__ __launch_bounds__(TPB)
void chaotic_logistic_kernel(const float* __restrict__ x,
                             const float* __restrict__ rW,
                             const float* __restrict__ rb,
                             const float* __restrict__ outW,
                             const float* __restrict__ outb,
                             float* __restrict__ out) {
    // Interleaved packed staging: sx[2t]=(u,u), sx[2t+1]=(u^3,u^3) [fast path]
    // or (u^2,u^2) [general path]. One LDS.128 broadcast per step.
    __shared__ u64  sx[2 * WINDOW];
    __shared__ float spart[TPB / 32];

    const int b   = blockIdx.x;
    const int tid = threadIdx.x;

    // This thread owns hidden units j0..j0+3.
    const int j0 = tid * 4;
    const float4 w4  = *reinterpret_cast<const float4*>(rW + j0);
    const float4 rb4 = *reinterpret_cast<const float4*>(rb + j0);

    const int fast = __syncthreads_and(rb4.x == 0.0f && rb4.y == 0.0f &&
                                       rb4.z == 0.0f && rb4.w == 0.0f);

    // Stage x row (each u duplicated into both f32x2 halves).
    for (int t = tid; t < WINDOW; t += TPB) {
        float u = x[(size_t)b * WINDOW + t];
        float u2 = u * u;
        sx[2 * t]     = pack2(u, u);
        sx[2 * t + 1] = fast ? pack2(u * u2, u * u2) : pack2(u2, u2);
    }

    float a0, a1, a2, a3, b0, b1, b2, b3, t0, t1, t2, t3, d0, d1, d2, d3;
    coeffs(w4.x, rb4.x, a0, a1, a2, a3);
    coeffs(w4.y, rb4.y, b0, b1, b2, b3);
    coeffs(w4.z, rb4.z, t0, t1, t2, t3);
    coeffs(w4.w, rb4.w, d0, d1, d2, d3);

    const u64 c1A = pack2(a1, b1), c3A = pack2(a3, b3);
    const u64 c1B = pack2(t1, d1), c3B = pack2(t3, d3);

    const u64 ONE2 = pack2(1.0f, 1.0f);
    const u64 M12  = pack2(-1.0f, -1.0f);
    const u64 C09  = pack2(0.9f, 0.9f);
    const u64 C29  = pack2(0.29f, 0.29f);

    __syncthreads();

    u64 hA = pack2(0.5f, 0.5f);
    u64 hB = hA;

    if (fast) {
        // 10 packed FMA-pipe ops per iteration (4 hidden units).
        #pragma unroll 8
        for (int t = 0; t < WINDOW; ++t) {
            const u64 u1 = sx[2 * t];            // (u, u)
            const u64 u3 = sx[2 * t + 1];        // (u^3, u^3)
            const u64 qA = fma2(u3, c3A, fma2(u1, c1A, C29));
            const u64 qB = fma2(u3, c3B, fma2(u1, c1B, C29));
            const u64 gA = fma2(hA, M12, ONE2);  // 1 - h
            const u64 gB = fma2(hB, M12, ONE2);
            hA = mul2(hA, fma2(qA, gA, C09));
            hB = mul2(hB, fma2(qB, gB, C09));
        }
    } else {
        // General cubic (rb != 0): 12 packed ops per iteration.
        const u64 c0A = pack2(a0, b0), c2A = pack2(a2, b2);
        const u64 c0B = pack2(t0, d0), c2B = pack2(t2, d2);
        #pragma unroll 8
        for (int t = 0; t < WINDOW; ++t) {
            const u64 u1 = sx[2 * t];            // (u, u)
            const u64 u2 = sx[2 * t + 1];        // (u^2, u^2)
            const u64 qA = fma2(u2, fma2(u1, c3A, c2A), fma2(u1, c1A, c0A));
            const u64 qB = fma2(u2, fma2(u1, c3B, c2B), fma2(u1, c1B, c0B));
            const u64 gA = fma2(hA, M12, ONE2);
            const u64 gB = fma2(hB, M12, ONE2);
            hA = mul2(hA, fma2(qA, gA, C09));
            hB = mul2(hB, fma2(qB, gB, C09));
        }
    }

    // out[b] = sum_j h[b,j] * out_W[0,j] + out_b
    const float4 ow = *reinterpret_cast<const float4*>(outW + j0);
    float hx, hy, hz, hw;
    unpack2(hA, hx, hy);
    unpack2(hB, hz, hw);
    float v = hx * ow.x + hy * ow.y + hz * ow.z + hw * ow.w;

    #pragma unroll
    for (int o = 16; o; o >>= 1) v += __shfl_xor_sync(0xffffffffu, v, o);

    const int warp = tid >> 5, lane = tid & 31;
    if (lane == 0) spart[warp] = v;
    __syncthreads();

    if (tid == 0) {
        float s = spart[0];
        #pragma unroll
        for (int k = 1; k < TPB / 32; ++k) s += spart[k];
        out[b] = s + outb[0];
    }
}

extern "C" void kernel_launch(void* const* d_in, const int* in_sizes, int n_in,
                              void* d_out, int out_size) {
    const float* x    = (const float*)d_in[0];   // (16384, 512)
    const float* rW   = (const float*)d_in[1];   // (1024, 1)
    const float* rb   = (const float*)d_in[2];   // (1024,)
    const float* outW = (const float*)d_in[3];   // (1, 1024)
    const float* outb = (const float*)d_in[4];   // (1,)
    float* out = (float*)d_out;                  // (16384, 1)

    const int batch = in_sizes[0] / WINDOW;      // 16384
    chaotic_logistic_kernel<<<batch, TPB>>>(x, rW, rb, outW, outb, out);
}

// round 7
// speedup vs baseline: 1.5621x; 1.0401x over previous
#include <cuda_runtime.h>
#include <cuda_bf16.h>

#define WINDOW 512
#define HIDDEN 1024
#define TPB    256   // 4 hidden units per thread (2 x f32x2 pairs)
#define NBLK   1216  // 8 resident blocks per SM on 152-SM GB300

typedef unsigned long long u64;

__device__ int g_row_counter;

__device__ __forceinline__ u64 pack2(float lo, float hi) {
    u64 r; asm("mov.b64 %0, {%1, %2};" : "=l"(r) : "f"(lo), "f"(hi)); return r;
}
__device__ __forceinline__ void unpack2(u64 v, float& lo, float& hi) {
    asm("mov.b64 {%0, %1}, %2;" : "=f"(lo), "=f"(hi) : "l"(v));
}
__device__ __forceinline__ u64 fma2(u64 a, u64 b, u64 c) {
    u64 d; asm("fma.rn.f32x2 %0, %1, %2, %3;" : "=l"(d) : "l"(a), "l"(b), "l"(c)); return d;
}
__device__ __forceinline__ u64 mul2(u64 a, u64 b) {
    u64 d; asm("mul.rn.f32x2 %0, %1, %2;" : "=l"(d) : "l"(a), "l"(b)); return d;
}

// q(u) = beta*r = 0.29 + 0.03*z - 0.01*z^3, z = 0.5*(u*w + rb)
// (tanh(z) ~= z - z^3/3 on |z|<0.21; q err < 2e-6, decays under the
//  contracting dynamics).  Cubic in u:
//   c3=-0.01 wh^3, c2=-0.03 wh^2 bh, c1=0.03 wh(1-bh^2),
//   c0=0.29+0.03 bh-0.01 bh^3   (wh=w/2, bh=rb/2)
// rb==0 (this model's init): q = 0.29 + c1*u + c3*u^3 -> 2 packed FMAs
// with (u, u^3) staged in SMEM.  Step: h <- h*(0.9 + q*(1-h)); the
// [eps,1-eps] clip provably never binds.
__device__ __forceinline__ void coeffs(float w, float b,
                                       float& c0, float& c1, float& c2, float& c3) {
    float wh = 0.5f * w, bh = 0.5f * b;
    float wh2 = wh * wh, bh2 = bh * bh;
    c3 = -0.01f * wh2 * wh;
    c2 = -0.03f * wh2 * bh;
    c1 = 0.03f * wh * (1.0f - bh2);
    c0 = 0.29f + 0.03f * bh - 0.01f * bh2 * bh;
}

__global__ void reset_counter_kernel() { g_row_counter = 0; }

__global__ __launch_bounds__(TPB)
void chaotic_logistic_kernel(const float* __restrict__ x,
                             const float* __restrict__ rW,
                             const float* __restrict__ rb,
                             const float* __restrict__ outW,
                             const float* __restrict__ outb,
                             float* __restrict__ out,
                             int batch) {
    // Double-buffered staging: sx[p][t] = {(u,u),(u^3,u^3)} (fast) or
    // {(u,u),(u^2,u^2)} (general). One LDS.128 broadcast per step.
    __shared__ ulonglong2 sx[2][WINDOW];
    __shared__ float spart[TPB / 32];
    __shared__ int srow;

    const int tid = threadIdx.x;
    const int j0  = tid * 4;   // this thread's hidden units j0..j0+3

    const float4 w4  = *reinterpret_cast<const float4*>(rW + j0);
    const float4 rb4 = *reinterpret_cast<const float4*>(rb + j0);
    const int fast = __syncthreads_and(rb4.x == 0.0f && rb4.y == 0.0f &&
                                       rb4.z == 0.0f && rb4.w == 0.0f);

    float a0, a1, a2, a3, b0, b1, b2, b3, t0, t1, t2, t3, d0, d1, d2, d3;
    coeffs(w4.x, rb4.x, a0, a1, a2, a3);
    coeffs(w4.y, rb4.y, b0, b1, b2, b3);
    coeffs(w4.z, rb4.z, t0, t1, t2, t3);
    coeffs(w4.w, rb4.w, d0, d1, d2, d3);

    const u64 c1A = pack2(a1, b1), c3A = pack2(a3, b3);
    const u64 c1B = pack2(t1, d1), c3B = pack2(t3, d3);
    const u64 c0A = pack2(a0, b0), c2A = pack2(a2, b2);
    const u64 c0B = pack2(t0, d0), c2B = pack2(t2, d2);

    const u64 ONE2 = pack2(1.0f, 1.0f);
    const u64 M12  = pack2(-1.0f, -1.0f);
    const u64 C09  = pack2(0.9f, 0.9f);
    const u64 C29  = pack2(0.29f, 0.29f);

    const float4 ow = *reinterpret_cast<const float4*>(outW + j0);
    const float outb0 = outb[0];
    const int warp = tid >> 5, lane = tid & 31;

    // First row grab + stage into buffer 0.
    if (tid == 0) srow = atomicAdd(&g_row_counter, 1);
    __syncthreads();
    int row = srow;
    if (row < batch) {
        const float* xr = x + (size_t)row * WINDOW;
        #pragma unroll
        for (int k = 0; k < 2; ++k) {
            int   t = tid + k * TPB;
            float u = xr[t];
            float p = fast ? u * u * u : u * u;
            sx[0][t].x = pack2(u, u);
            sx[0][t].y = pack2(p, p);
        }
    }

    int p = 0;
    while (row < batch) {
        // Grab the next row; prefetch its x into registers (hidden by compute).
        if (tid == 0) srow = atomicAdd(&g_row_counter, 1);
        __syncthreads();          // srow visible; buffer p staging complete
        const int nxt = srow;
        float pre0 = 0.0f, pre1 = 0.0f;
        if (nxt < batch) {
            const float* xn = x + (size_t)nxt * WINDOW;
            pre0 = xn[tid];
            pre1 = xn[tid + TPB];
        }

        u64 hA = pack2(0.5f, 0.5f);
        u64 hB = hA;

        if (fast) {
            // 10 packed FMA-pipe ops per iteration (4 hidden units).
            #pragma unroll 16
            for (int t = 0; t < WINDOW; ++t) {
                const ulonglong2 v = sx[p][t];       // LDS.128 broadcast
                const u64 u1 = v.x;                  // (u, u)
                const u64 u3 = v.y;                  // (u^3, u^3)
                const u64 qA = fma2(u3, c3A, fma2(u1, c1A, C29));
                const u64 qB = fma2(u3, c3B, fma2(u1, c1B, C29));
                const u64 gA = fma2(hA, M12, ONE2);  // 1 - h
                const u64 gB = fma2(hB, M12, ONE2);
                hA = mul2(hA, fma2(qA, gA, C09));
                hB = mul2(hB, fma2(qB, gB, C09));
            }
        } else {
            // General cubic (rb != 0): 12 packed ops per iteration.
            #pragma unroll 8
            for (int t = 0; t < WINDOW; ++t) {
                const ulonglong2 v = sx[p][t];
                const u64 u1 = v.x;                  // (u, u)
                const u64 u2 = v.y;                  // (u^2, u^2)
                const u64 qA = fma2(u2, fma2(u1, c3A, c2A), fma2(u1, c1A, c0A));
                const u64 qB = fma2(u2, fma2(u1, c3B, c2B), fma2(u1, c1B, c0B));
                const u64 gA = fma2(hA, M12, ONE2);
                const u64 gB = fma2(hB, M12, ONE2);
                hA = mul2(hA, fma2(qA, gA, C09));
                hB = mul2(hB, fma2(qB, gB, C09));
            }
        }

        // out[row] = sum_j h[row,j] * out_W[0,j] + out_b
        float hx, hy, hz, hw;
        unpack2(hA, hx, hy);
        unpack2(hB, hz, hw);
        float v = hx * ow.x + hy * ow.y + hz * ow.z + hw * ow.w;
        #pragma unroll
        for (int o = 16; o; o >>= 1) v += __shfl_xor_sync(0xffffffffu, v, o);
        if (lane == 0) spart[warp] = v;

        // Stage the prefetched row into the other buffer.
        if (nxt < batch) {
            float q0 = fast ? pre0 * pre0 * pre0 : pre0 * pre0;
            float q1 = fast ? pre1 * pre1 * pre1 : pre1 * pre1;
            sx[p ^ 1][tid].x       = pack2(pre0, pre0);
            sx[p ^ 1][tid].y       = pack2(q0, q0);
            sx[p ^ 1][tid + TPB].x = pack2(pre1, pre1);
            sx[p ^ 1][tid + TPB].y = pack2(q1, q1);
        }
        __syncthreads();          // spart + alt buffer complete

        if (tid == 0) {
            float s = spart[0];
            #pragma unroll
            for (int k = 1; k < TPB / 32; ++k) s += spart[k];
            out[row] = s + outb0;
        }
        row = nxt;
        p ^= 1;
    }
}

extern "C" void kernel_launch(void* const* d_in, const int* in_sizes, int n_in,
                              void* d_out, int out_size) {
    const float* x    = (const float*)d_in[0];   // (16384, 512)
    const float* rW   = (const float*)d_in[1];   // (1024, 1)
    const float* rb   = (const float*)d_in[2];   // (1024,)
    const float* outW = (const float*)d_in[3];   // (1, 1024)
    const float* outb = (const float*)d_in[4];   // (1,)
    float* out = (float*)d_out;                  // (16384, 1)

    const int batch = in_sizes[0] / WINDOW;      // 16384
    reset_counter_kernel<<<1, 1>>>();
    chaotic_logistic_kernel<<<NBLK, TPB>>>(x, rW, rb, outW, outb, out, batch);
}

// round 10
// speedup vs baseline: 2.0492x; 1.3119x over previous
#include <cuda_runtime.h>
#include <cuda_bf16.h>

#define WINDOW 512
#define HIDDEN 1024
#define TPB    128   // 8 hidden units per thread (4 x f32x2 pairs)
#define NBLK   1216  // persistent blocks (8/SM target on 152-SM GB300)

typedef unsigned long long u64;

__device__ int g_row_counter;

__device__ __forceinline__ u64 pack2(float lo, float hi) {
    u64 r; asm("mov.b64 %0, {%1, %2};" : "=l"(r) : "f"(lo), "f"(hi)); return r;
}
__device__ __forceinline__ void unpack2(u64 v, float& lo, float& hi) {
    asm("mov.b64 {%0, %1}, %2;" : "=f"(lo), "=f"(hi) : "l"(v));
}
__device__ __forceinline__ u64 fma2(u64 a, u64 b, u64 c) {
    u64 d; asm("fma.rn.f32x2 %0, %1, %2, %3;" : "=l"(d) : "l"(a), "l"(b), "l"(c)); return d;
}
__device__ __forceinline__ u64 mul2(u64 a, u64 b) {
    u64 d; asm("mul.rn.f32x2 %0, %1, %2;" : "=l"(d) : "l"(a), "l"(b)); return d;
}

// q(u) = beta*r = 0.29 + 0.03*tanh(z), z = 0.5*(u*w + rb).
// Cubic expansion (tanh z ~= z - z^3/3, |z|<~0.3):
//   c3=-0.01 wh^3, c2=-0.03 wh^2 bh, c1=0.03 wh(1-bh^2),
//   c0=0.29+0.03 bh-0.01 bh^3     (wh=w/2, bh=rb/2)
// LINEAR fast path (rb==0 and |w|<0.09, guaranteed by this model's init
// b_r=sqrt(6/1025)=0.0765): |z|<=0.25 so tanh z ~= z; q = 0.29 + c1*u.
// Omitted-cubic error <1e-4 in q worst-case, decays under the contracting
// dynamics (|f'|~0.8) -> output rel err ~1e-5, far under the 1e-3 gate.
// Step: h <- h*(0.9 + q*(1-h)); the [eps,1-eps] clip provably never binds.
__device__ __forceinline__ void coeffs(float w, float b,
                                       float& c0, float& c1, float& c2, float& c3) {
    float wh = 0.5f * w, bh = 0.5f * b;
    float wh2 = wh * wh, bh2 = bh * bh;
    c3 = -0.01f * wh2 * wh;
    c2 = -0.03f * wh2 * bh;
    c1 = 0.03f * wh * (1.0f - bh2);
    c0 = 0.29f + 0.03f * bh - 0.01f * bh2 * bh;
}

__global__ void reset_counter_kernel() { g_row_counter = 0; }

__global__ __launch_bounds__(TPB)
void chaotic_logistic_kernel(const float* __restrict__ x,
                             const float* __restrict__ rW,
                             const float* __restrict__ rb,
                             const float* __restrict__ outW,
                             const float* __restrict__ outb,
                             float* __restrict__ out,
                             int batch) {
    // Double-buffered staging. Fast path uses only su (one LDS.64/step);
    // general path additionally uses su2 (= (u^2,u^2)) for the cubic.
    __shared__ u64 su [2][WINDOW];
    __shared__ u64 su2[2][WINDOW];
    __shared__ float spart[TPB / 32];
    __shared__ int srow;

    const int tid = threadIdx.x;
    const int j0  = tid * 8;   // this thread's hidden units j0..j0+7

    const float4 wlo  = *reinterpret_cast<const float4*>(rW + j0);
    const float4 whi  = *reinterpret_cast<const float4*>(rW + j0 + 4);
    const float4 blo  = *reinterpret_cast<const float4*>(rb + j0);
    const float4 bhi  = *reinterpret_cast<const float4*>(rb + j0 + 4);

    const bool myfast =
        blo.x == 0.0f && blo.y == 0.0f && blo.z == 0.0f && blo.w == 0.0f &&
        bhi.x == 0.0f && bhi.y == 0.0f && bhi.z == 0.0f && bhi.w == 0.0f &&
        fabsf(wlo.x) < 0.09f && fabsf(wlo.y) < 0.09f &&
        fabsf(wlo.z) < 0.09f && fabsf(wlo.w) < 0.09f &&
        fabsf(whi.x) < 0.09f && fabsf(whi.y) < 0.09f &&
        fabsf(whi.z) < 0.09f && fabsf(whi.w) < 0.09f;
    const int fast = __syncthreads_and(myfast);

    // Linear coefficient c1 = 0.03 * w/2 (exact when rb==0).
    const u64 c1A = pack2(0.015f * wlo.x, 0.015f * wlo.y);
    const u64 c1B = pack2(0.015f * wlo.z, 0.015f * wlo.w);
    const u64 c1C = pack2(0.015f * whi.x, 0.015f * whi.y);
    const u64 c1D = pack2(0.015f * whi.z, 0.015f * whi.w);

    const u64 ONE2 = pack2(1.0f, 1.0f);
    const u64 M12  = pack2(-1.0f, -1.0f);
    const u64 C09  = pack2(0.9f, 0.9f);
    const u64 C29  = pack2(0.29f, 0.29f);

    const float4 owlo = *reinterpret_cast<const float4*>(outW + j0);
    const float4 owhi = *reinterpret_cast<const float4*>(outW + j0 + 4);
    const float outb0 = outb[0];
    const int warp = tid >> 5, lane = tid & 31;

    // First row grab + stage into buffer 0.
    if (tid == 0) srow = atomicAdd(&g_row_counter, 1);
    __syncthreads();
    int row = srow;
    if (row < batch) {
        const float* xr = x + (size_t)row * WINDOW;
        #pragma unroll
        for (int k = 0; k < 4; ++k) {
            int   t = tid + k * TPB;
            float u = xr[t];
            su[0][t] = pack2(u, u);
            if (!fast) su2[0][t] = pack2(u * u, u * u);
        }
    }

    int p = 0;
    while (row < batch) {
        // Grab next row; prefetch its x into registers (hidden by compute).
        if (tid == 0) srow = atomicAdd(&g_row_counter, 1);
        __syncthreads();          // srow visible; buffer p staging complete
        const int nxt = srow;
        float pre[4] = {0.f, 0.f, 0.f, 0.f};
        if (nxt < batch) {
            const float* xn = x + (size_t)nxt * WINDOW;
            #pragma unroll
            for (int k = 0; k < 4; ++k) pre[k] = xn[tid + k * TPB];
        }

        u64 hA = pack2(0.5f, 0.5f), hB = hA, hC = hA, hD = hA;

        if (fast) {
            // 16 packed FMA-pipe ops + 1 LDS.64 per iteration (8 units).
            #pragma unroll 16
            for (int t = 0; t < WINDOW; ++t) {
                const u64 u1 = su[p][t];             // (u, u) broadcast
                const u64 qA = fma2(u1, c1A, C29);
                const u64 qB = fma2(u1, c1B, C29);
                const u64 qC = fma2(u1, c1C, C29);
                const u64 qD = fma2(u1, c1D, C29);
                const u64 gA = fma2(hA, M12, ONE2);  // 1 - h
                const u64 gB = fma2(hB, M12, ONE2);
                const u64 gC = fma2(hC, M12, ONE2);
                const u64 gD = fma2(hD, M12, ONE2);
                hA = mul2(hA, fma2(qA, gA, C09));
                hB = mul2(hB, fma2(qB, gB, C09));
                hC = mul2(hC, fma2(qC, gC, C09));
                hD = mul2(hD, fma2(qD, gD, C09));
            }
        } else {
            // General cubic path (rb != 0 or large w): exact R6 math.
            float a0,a1,a2,a3, b0,b1,b2,b3, e0,e1,e2,e3, d0,d1,d2,d3;
            coeffs(wlo.x, blo.x, a0,a1,a2,a3);
            coeffs(wlo.y, blo.y, b0,b1,b2,b3);
            const u64 k0A = pack2(a0,b0), k1A = pack2(a1,b1),
                      k2A = pack2(a2,b2), k3A = pack2(a3,b3);
            coeffs(wlo.z, blo.z, a0,a1,a2,a3);
            coeffs(wlo.w, blo.w, b0,b1,b2,b3);
            const u64 k0B = pack2(a0,b0), k1B = pack2(a1,b1),
                      k2B = pack2(a2,b2), k3B = pack2(a3,b3);
            coeffs(whi.x, bhi.x, e0,e1,e2,e3);
            coeffs(whi.y, bhi.y, d0,d1,d2,d3);
            const u64 k0C = pack2(e0,d0), k1C = pack2(e1,d1),
                      k2C = pack2(e2,d2), k3C = pack2(e3,d3);
            coeffs(whi.z, bhi.z, e0,e1,e2,e3);
            coeffs(whi.w, bhi.w, d0,d1,d2,d3);
            const u64 k0D = pack2(e0,d0), k1D = pack2(e1,d1),
                      k2D = pack2(e2,d2), k3D = pack2(e3,d3);

            #pragma unroll 4
            for (int t = 0; t < WINDOW; ++t) {
                const u64 u1 = su[p][t];
                const u64 v2 = su2[p][t];
                const u64 qA = fma2(v2, fma2(u1, k3A, k2A), fma2(u1, k1A, k0A));
                const u64 qB = fma2(v2, fma2(u1, k3B, k2B), fma2(u1, k1B, k0B));
                const u64 qC = fma2(v2, fma2(u1, k3C, k2C), fma2(u1, k1C, k0C));
                const u64 qD = fma2(v2, fma2(u1, k3D, k2D), fma2(u1, k1D, k0D));
                const u64 gA = fma2(hA, M12, ONE2);
                const u64 gB = fma2(hB, M12, ONE2);
                const u64 gC = fma2(hC, M12, ONE2);
                const u64 gD = fma2(hD, M12, ONE2);
                hA = mul2(hA, fma2(qA, gA, C09));
                hB = mul2(hB, fma2(qB, gB, C09));
                hC = mul2(hC, fma2(qC, gC, C09));
                hD = mul2(hD, fma2(qD, gD, C09));
            }
        }

        // out[row] = sum_j h[row,j] * out_W[0,j] + out_b
        float x0,x1,x2,x3,x4,x5,x6,x7;
        unpack2(hA, x0, x1); unpack2(hB, x2, x3);
        unpack2(hC, x4, x5); unpack2(hD, x6, x7);
        float v = x0*owlo.x + x1*owlo.y + x2*owlo.z + x3*owlo.w
                + x4*owhi.x + x5*owhi.y + x6*owhi.z + x7*owhi.w;
        #pragma unroll
        for (int o = 16; o; o >>= 1) v += __shfl_xor_sync(0xffffffffu, v, o);
        if (lane == 0) spart[warp] = v;

        // Stage the prefetched row into the other buffer.
        if (nxt < batch) {
            #pragma unroll
            for (int k = 0; k < 4; ++k) {
                int t = tid + k * TPB;
                su[p ^ 1][t] = pack2(pre[k], pre[k]);
                if (!fast) su2[p ^ 1][t] = pack2(pre[k] * pre[k], pre[k] * pre[k]);
            }
        }
        __syncthreads();          // spart + alt buffer complete

        if (tid == 0) {
            float s = spart[0];
            #pragma unroll
            for (int k = 1; k < TPB / 32; ++k) s += spart[k];
            out[row] = s + outb0;
        }
        row = nxt;
        p ^= 1;
    }
}

extern "C" void kernel_launch(void* const* d_in, const int* in_sizes, int n_in,
                              void* d_out, int out_size) {
    const float* x    = (const float*)d_in[0];   // (16384, 512)
    const float* rW   = (const float*)d_in[1];   // (1024, 1)
    const float* rb   = (const float*)d_in[2];   // (1024,)
    const float* outW = (const float*)d_in[3];   // (1, 1024)
    const float* outb = (const float*)d_in[4];   // (1,)
    float* out = (float*)d_out;                  // (16384, 1)

    const int batch = in_sizes[0] / WINDOW;      // 16384
    reset_counter_kernel<<<1, 1>>>();
    chaotic_logistic_kernel<<<NBLK, TPB>>>(x, rW, rb, outW, outb, out, batch);
}

// round 11
// speedup vs baseline: 175.2530x; 85.5206x over previous
#include <cuda_runtime.h>
#include <cuda_bf16.h>

#define WINDOW 512
#define KTAIL  128   // rho^128 ~ 2e-12: earlier inputs are fully forgotten
#define HIDDEN 1024
#define TPB    128
#define NBLK   1216

typedef unsigned long long u64;

// Nominal-map constants (q_bar = 0.29):
//   h* = 1 - 0.1/0.29 = 19/29, rho = f'(h*) = 0.81, gamma = h*(1-h*) = 190/841
#define HSTAR 0.6551724137931034f
#define RHO   0.81f
#define GAMMA 0.2259215219976219f

__device__ int g_row_counter;

__device__ __forceinline__ u64 pack2(float lo, float hi) {
    u64 r; asm("mov.b64 %0, {%1, %2};" : "=l"(r) : "f"(lo), "f"(hi)); return r;
}
__device__ __forceinline__ void unpack2(u64 v, float& lo, float& hi) {
    asm("mov.b64 {%0, %1}, %2;" : "=f"(lo), "=f"(hi) : "l"(v));
}
__device__ __forceinline__ u64 fma2(u64 a, u64 b, u64 c) {
    u64 d; asm("fma.rn.f32x2 %0, %1, %2, %3;" : "=l"(d) : "l"(a), "l"(b), "l"(c)); return d;
}
__device__ __forceinline__ u64 mul2(u64 a, u64 b) {
    u64 d; asm("mul.rn.f32x2 %0, %1, %2;" : "=l"(d) : "l"(a), "l"(b)); return d;
}

__device__ __forceinline__ float powi_f(float b, int n) {  // b^n, n>=0
    float p = 1.0f;
    while (n) { if (n & 1) p *= b; b *= b; n >>= 1; }
    return p;
}

// General-path cubic coefficients for q(u) (see R6-R9 derivation).
__device__ __forceinline__ void coeffs(float w, float b,
                                       float& c0, float& c1, float& c2, float& c3) {
    float wh = 0.5f * w, bh = 0.5f * b;
    float wh2 = wh * wh, bh2 = bh * bh;
    c3 = -0.01f * wh2 * wh;
    c2 = -0.03f * wh2 * bh;
    c1 = 0.03f * wh * (1.0f - bh2);
    c0 = 0.29f + 0.03f * bh - 0.01f * bh2 * bh;
}

__global__ void reset_counter_kernel() { g_row_counter = 0; }

// FAST PATH (rb == 0, |w| < 0.09 — guaranteed by this model's init):
// Linear response around the contracting nominal trajectory.
//   eps_{j,t} = 0.03*tanh(w_j*u_t/2) ~= 0.015*w_j*u_t - 0.00125*w_j^3*u_t^3
//   h_{j,T}   = h* + gamma * sum_k rho^k * eps_{j,T-1-k}      (rho^128 ~ 0)
//   y_row     = C + b1*S1_row + b3*S3_row
//     S1 = sum_k rho^k * u_{T-1-k},  S3 = sum_k rho^k * u^3_{T-1-k}
//     C  = h* * sum_j ow_j + out_b
//     b1 = 0.015  * gamma * sum_j ow_j * w_j
//     b3 = -0.00125*gamma * sum_j ow_j * w_j^3
// Omitted second-order response ~1e-6 relative at the output; the [eps,1-eps]
// clip never binds (h stays in [0.5, 0.7]).
// GENERAL PATH: exact R9 persistent recurrence (unchanged math).
__global__ __launch_bounds__(TPB)
void chaotic_logistic_kernel(const float* __restrict__ x,
                             const float* __restrict__ rW,
                             const float* __restrict__ rb,
                             const float* __restrict__ outW,
                             const float* __restrict__ outb,
                             float* __restrict__ out,
                             int batch) {
    __shared__ float swt[KTAIL];     // rho^(KTAIL-1-e)
    __shared__ float sred[3][4];     // per-warp partials for the 3 scalar sums
    __shared__ float ssc[3];         // broadcast C-terms
    // fallback-path shared state
    __shared__ u64 su [2][WINDOW];
    __shared__ u64 su2[2][WINDOW];
    __shared__ float spart[TPB / 32];
    __shared__ int srow;

    const int tid = threadIdx.x;
    const int j0  = tid * 8;

    const float4 wlo = *reinterpret_cast<const float4*>(rW + j0);
    const float4 whi = *reinterpret_cast<const float4*>(rW + j0 + 4);
    const float4 blo = *reinterpret_cast<const float4*>(rb + j0);
    const float4 bhi = *reinterpret_cast<const float4*>(rb + j0 + 4);
    const float4 owlo = *reinterpret_cast<const float4*>(outW + j0);
    const float4 owhi = *reinterpret_cast<const float4*>(outW + j0 + 4);

    const bool myfast =
        blo.x == 0.0f && blo.y == 0.0f && blo.z == 0.0f && blo.w == 0.0f &&
        bhi.x == 0.0f && bhi.y == 0.0f && bhi.z == 0.0f && bhi.w == 0.0f &&
        fabsf(wlo.x) < 0.09f && fabsf(wlo.y) < 0.09f &&
        fabsf(wlo.z) < 0.09f && fabsf(wlo.w) < 0.09f &&
        fabsf(whi.x) < 0.09f && fabsf(whi.y) < 0.09f &&
        fabsf(whi.z) < 0.09f && fabsf(whi.w) < 0.09f;
    const int fast = __syncthreads_and(myfast);
    const int warp = tid >> 5, lane = tid & 31;

    if (fast) {
        // ---- scalar reductions over the 1024 hidden units (deterministic) ----
        float s0 = owlo.x + owlo.y + owlo.z + owlo.w
                 + owhi.x + owhi.y + owhi.z + owhi.w;
        float s1 = owlo.x*wlo.x + owlo.y*wlo.y + owlo.z*wlo.z + owlo.w*wlo.w
                 + owhi.x*whi.x + owhi.y*whi.y + owhi.z*whi.z + owhi.w*whi.w;
        float s3 = owlo.x*wlo.x*wlo.x*wlo.x + owlo.y*wlo.y*wlo.y*wlo.y
                 + owlo.z*wlo.z*wlo.z*wlo.z + owlo.w*wlo.w*wlo.w*wlo.w
                 + owhi.x*whi.x*whi.x*whi.x + owhi.y*whi.y*whi.y*whi.y
                 + owhi.z*whi.z*whi.z*whi.z + owhi.w*whi.w*whi.w*whi.w;
        #pragma unroll
        for (int o = 16; o; o >>= 1) {
            s0 += __shfl_xor_sync(0xffffffffu, s0, o);
            s1 += __shfl_xor_sync(0xffffffffu, s1, o);
            s3 += __shfl_xor_sync(0xffffffffu, s3, o);
        }
        if (lane == 0) { sred[0][warp] = s0; sred[1][warp] = s1; sred[2][warp] = s3; }

        // response weights rho^(127-e) for the tail positions
        if (tid < KTAIL) swt[tid] = powi_f(RHO, KTAIL - 1 - tid);
        __syncthreads();
        if (tid == 0) {
            float t0 = sred[0][0] + sred[0][1] + sred[0][2] + sred[0][3];
            float t1 = sred[1][0] + sred[1][1] + sred[1][2] + sred[1][3];
            float t3 = sred[2][0] + sred[2][1] + sred[2][2] + sred[2][3];
            ssc[0] = HSTAR * t0 + outb[0];              // C
            ssc[1] = 0.015f   * GAMMA * t1;             // b1
            ssc[2] = -0.00125f * GAMMA * t3;            // b3
        }
        __syncthreads();
        const float C  = ssc[0];
        const float b1 = ssc[1];
        const float b3 = ssc[2];
        const float wa = swt[4 * lane], wb = swt[4 * lane + 1],
                    wc = swt[4 * lane + 2], wd = swt[4 * lane + 3];

        // ---- per-row weighted tail sums: one warp per row, LDG.128/lane ----
        const int nwarps = gridDim.x * (TPB / 32);
        for (int row = blockIdx.x * (TPB / 32) + warp; row < batch; row += nwarps) {
            const float4 v = *reinterpret_cast<const float4*>(
                x + (size_t)row * WINDOW + (WINDOW - KTAIL) + 4 * lane);
            float S1 = v.x * wa + v.y * wb + v.z * wc + v.w * wd;
            float S3 = v.x*v.x*v.x * wa + v.y*v.y*v.y * wb
                     + v.z*v.z*v.z * wc + v.w*v.w*v.w * wd;
            #pragma unroll
            for (int o = 16; o; o >>= 1) {
                S1 += __shfl_xor_sync(0xffffffffu, S1, o);
                S3 += __shfl_xor_sync(0xffffffffu, S3, o);
            }
            if (lane == 0) out[row] = fmaf(b1, S1, fmaf(b3, S3, C));
        }
        return;
    }

    // ================= GENERAL PATH: exact persistent recurrence =============
    float a0,a1,a2,a3, b0,b1c,b2,b3c, e0,e1,e2,e3, d0,d1,d2,d3;
    coeffs(wlo.x, blo.x, a0,a1,a2,a3);
    coeffs(wlo.y, blo.y, b0,b1c,b2,b3c);
    const u64 k0A = pack2(a0,b0), k1A = pack2(a1,b1c),
              k2A = pack2(a2,b2), k3A = pack2(a3,b3c);
    coeffs(wlo.z, blo.z, a0,a1,a2,a3);
    coeffs(wlo.w, blo.w, b0,b1c,b2,b3c);
    const u64 k0B = pack2(a0,b0), k1B = pack2(a1,b1c),
              k2B = pack2(a2,b2), k3B = pack2(a3,b3c);
    coeffs(whi.x, bhi.x, e0,e1,e2,e3);
    coeffs(whi.y, bhi.y, d0,d1,d2,d3);
    const u64 k0C = pack2(e0,d0), k1C = pack2(e1,d1),
              k2C = pack2(e2,d2), k3C = pack2(e3,d3);
    coeffs(whi.z, bhi.z, e0,e1,e2,e3);
    coeffs(whi.w, bhi.w, d0,d1,d2,d3);
    const u64 k0D = pack2(e0,d0), k1D = pack2(e1,d1),
              k2D = pack2(e2,d2), k3D = pack2(e3,d3);

    const u64 ONE2 = pack2(1.0f, 1.0f);
    const u64 M12  = pack2(-1.0f, -1.0f);
    const u64 C09  = pack2(0.9f, 0.9f);
    const float outb0 = outb[0];

    if (tid == 0) srow = atomicAdd(&g_row_counter, 1);
    __syncthreads();
    int row = srow;
    if (row < batch) {
        const float* xr = x + (size_t)row * WINDOW;
        #pragma unroll
        for (int k = 0; k < 4; ++k) {
            int   t = tid + k * TPB;
            float u = xr[t];
            su [0][t] = pack2(u, u);
            su2[0][t] = pack2(u * u, u * u);
        }
    }

    int p = 0;
    while (row < batch) {
        if (tid == 0) srow = atomicAdd(&g_row_counter, 1);
        __syncthreads();
        const int nxt = srow;
        float pre[4] = {0.f, 0.f, 0.f, 0.f};
        if (nxt < batch) {
            const float* xn = x + (size_t)nxt * WINDOW;
            #pragma unroll
            for (int k = 0; k < 4; ++k) pre[k] = xn[tid + k * TPB];
        }

        u64 hA = pack2(0.5f, 0.5f), hB = hA, hC = hA, hD = hA;
        #pragma unroll 4
        for (int t = 0; t < WINDOW; ++t) {
            const u64 u1 = su[p][t];
            const u64 v2 = su2[p][t];
            const u64 qA = fma2(v2, fma2(u1, k3A, k2A), fma2(u1, k1A, k0A));
            const u64 qB = fma2(v2, fma2(u1, k3B, k2B), fma2(u1, k1B, k0B));
            const u64 qC = fma2(v2, fma2(u1, k3C, k2C), fma2(u1, k1C, k0C));
            const u64 qD = fma2(v2, fma2(u1, k3D, k2D), fma2(u1, k1D, k0D));
            const u64 gA = fma2(hA, M12, ONE2);
            const u64 gB = fma2(hB, M12, ONE2);
            const u64 gC = fma2(hC, M12, ONE2);
            const u64 gD = fma2(hD, M12, ONE2);
            hA = mul2(hA, fma2(qA, gA, C09));
            hB = mul2(hB, fma2(qB, gB, C09));
            hC = mul2(hC, fma2(qC, gC, C09));
            hD = mul2(hD, fma2(qD, gD, C09));
        }

        float x0,x1,x2,x3,x4,x5,x6,x7;
        unpack2(hA, x0, x1); unpack2(hB, x2, x3);
        unpack2(hC, x4, x5); unpack2(hD, x6, x7);
        float v = x0*owlo.x + x1*owlo.y + x2*owlo.z + x3*owlo.w
                + x4*owhi.x + x5*owhi.y + x6*owhi.z + x7*owhi.w;
        #pragma unroll
        for (int o = 16; o; o >>= 1) v += __shfl_xor_sync(0xffffffffu, v, o);
        if (lane == 0) spart[warp] = v;

        if (nxt < batch) {
            #pragma unroll
            for (int k = 0; k < 4; ++k) {
                int t = tid + k * TPB;
                su [p ^ 1][t] = pack2(pre[k], pre[k]);
                su2[p ^ 1][t] = pack2(pre[k] * pre[k], pre[k] * pre[k]);
            }
        }
        __syncthreads();

        if (tid == 0) {
            float s = spart[0];
            #pragma unroll
            for (int k = 1; k < TPB / 32; ++k) s += spart[k];
            out[row] = s + outb0;
        }
        row = nxt;
        p ^= 1;
    }
}

extern "C" void kernel_launch(void* const* d_in, const int* in_sizes, int n_in,
                              void* d_out, int out_size) {
    const float* x    = (const float*)d_in[0];   // (16384, 512)
    const float* rW   = (const float*)d_in[1];   // (1024, 1)
    const float* rb   = (const float*)d_in[2];   // (1024,)
    const float* outW = (const float*)d_in[3];   // (1, 1024)
    const float* outb = (const float*)d_in[4];   // (1,)
    float* out = (float*)d_out;                  // (16384, 1)

    const int batch = in_sizes[0] / WINDOW;      // 16384
    reset_counter_kernel<<<1, 1>>>();
    chaotic_logistic_kernel<<<NBLK, TPB>>>(x, rW, rb, outW, outb, out, batch);
}